// round 12
// baseline (speedup 1.0000x reference)
#include <cuda_runtime.h>
#include <cuda_fp16.h>
#include <math.h>
#include <cstdint>

// Problem dims
#define NB 4
#define NS 2048
#define ND 512
#define NH 8
#define NHD 64
#define NF 2048
#define NROW (NB * NS)   // 8192
#define QLD 1536         // fused qkv row stride (halves)

// ---------------- scratch ----------------------------------------------------
__device__ __half g_wqkvth[1536 * 512];
__device__ float  g_bqkv[1536];
__device__ __half g_woth[512 * 512];
__device__ __half g_w1th[2048 * 512];
__device__ __half g_w2th[512 * 2048];
__device__ __half g_xh[NROW * ND];
__device__ __half g_qkvh[NROW * 1536];
__device__ __half g_attnh[NROW * ND];
__device__ float  g_res1[NROW * ND];
__device__ float  g_x1[NROW * ND];
__device__ __half g_x1h[NROW * ND];
__device__ __half g_hh[NROW * NF];
__device__ float  g_res2[NROW * ND];

// ---------------- helpers ----------------------------------------------------
__device__ __forceinline__ uint32_t smem_u32(const void* p) {
    uint32_t a;
    asm("{ .reg .u64 t; cvta.to.shared.u64 t, %1; cvt.u32.u64 %0, t; }" : "=r"(a) : "l"(p));
    return a;
}
__device__ __forceinline__ void cp_async16(uint32_t sa, const void* ga) {
    asm volatile("cp.async.cg.shared.global [%0], [%1], 16;" :: "r"(sa), "l"(ga) : "memory");
}
__device__ __forceinline__ void cp_commit() { asm volatile("cp.async.commit_group;" ::: "memory"); }
template <int N> __device__ __forceinline__ void cp_wait() {
    asm volatile("cp.async.wait_group %0;" :: "n"(N) : "memory");
}
// D += A*B  (m16n8k16 fp16 in, fp32 accum)
__device__ __forceinline__ void mma16(float* c, const uint32_t* a, const uint32_t* b) {
    asm volatile("mma.sync.aligned.m16n8k16.row.col.f32.f16.f16.f32 "
                 "{%0,%1,%2,%3}, {%4,%5,%6,%7}, {%8,%9}, {%0,%1,%2,%3};"
                 : "+f"(c[0]), "+f"(c[1]), "+f"(c[2]), "+f"(c[3])
                 : "r"(a[0]), "r"(a[1]), "r"(a[2]), "r"(a[3]), "r"(b[0]), "r"(b[1]));
}
__device__ __forceinline__ void ldsm4(uint32_t* r, uint32_t addr) {
    asm volatile("ldmatrix.sync.aligned.m8n8.x4.shared.b16 {%0,%1,%2,%3}, [%4];"
                 : "=r"(r[0]), "=r"(r[1]), "=r"(r[2]), "=r"(r[3]) : "r"(addr));
}
__device__ __forceinline__ void ldsm4t(uint32_t* r, uint32_t addr) {
    asm volatile("ldmatrix.sync.aligned.m8n8.x4.trans.shared.b16 {%0,%1,%2,%3}, [%4];"
                 : "=r"(r[0]), "=r"(r[1]), "=r"(r[2]), "=r"(r[3]) : "r"(addr));
}
__device__ __forceinline__ uint32_t f22u(float a, float b) {
    __half2 t = __floats2half2_rn(a, b);
    return *(uint32_t*)&t;
}

// ---------------- fused weight-transpose prep --------------------------------
// 1D grid of 3072 32x32 tiles:
//   [0,768)    : QKV pack  (24 slices x (16 k-tiles x 2 e-tiles))
//   [768,1024) : Wo   (K=512,  N=512)
//   [1024,2048): W1   (K=512,  N=2048)
//   [2048,3072): W2   (K=2048, N=512)
__global__ void prep_w_t(const float* __restrict__ Wq, const float* __restrict__ Wk,
                         const float* __restrict__ Wv, const float* __restrict__ Wo,
                         const float* __restrict__ W1, const float* __restrict__ W2,
                         __half* __restrict__ oqkv, __half* __restrict__ owo,
                         __half* __restrict__ ow1, __half* __restrict__ ow2) {
    __shared__ float tile[32][33];
    int id = blockIdx.x;
    const float* in;
    __half* out;
    int K, N, k0, n0;
    size_t outbase;
    if (id < 768) {
        int slice = id >> 5, rem = id & 31;
        int sel = slice >> 3, h = slice & 7;
        in = (sel == 0 ? Wq : (sel == 1 ? Wk : Wv)) + (size_t)h * 512 * 64;
        out = oqkv; K = 512; N = 64;
        k0 = (rem & 15) * 32; n0 = (rem >> 4) * 32;
        outbase = (size_t)(sel * 512 + h * 64);
    } else if (id < 1024) {
        int r = id - 768;
        in = Wo; out = owo; K = 512; N = 512;
        n0 = (r & 15) * 32; k0 = (r >> 4) * 32; outbase = 0;
    } else if (id < 2048) {
        int r = id - 1024;
        in = W1; out = ow1; K = 512; N = 2048;
        n0 = (r & 63) * 32; k0 = (r >> 6) * 32; outbase = 0;
    } else {
        int r = id - 2048;
        in = W2; out = ow2; K = 2048; N = 512;
        n0 = (r & 15) * 32; k0 = (r >> 4) * 32; outbase = 0;
    }
    int tx = threadIdx.x & 31, ty = threadIdx.x >> 5;
#pragma unroll
    for (int i = 0; i < 4; i++)
        tile[ty + i * 8][tx] = in[(size_t)(k0 + ty + i * 8) * N + n0 + tx];
    __syncthreads();
#pragma unroll
    for (int i = 0; i < 4; i++)
        out[(outbase + n0 + ty + i * 8) * (size_t)K + k0 + tx] =
            __float2half_rn(tile[tx][ty + i * 8]);
}
__global__ void pack_qkvb_kernel(const float* __restrict__ bq, const float* __restrict__ bk,
                                 const float* __restrict__ bv, float* __restrict__ out) {
    int n = blockIdx.x * 256 + threadIdx.x;
    if (n >= 1536) return;
    int sel = n >> 9, r = n & 511;
    const float* b = sel == 0 ? bq : (sel == 1 ? bk : bv);
    out[n] = b[r];
}
__global__ void cvt_half_kernel(const float* __restrict__ in, __half* __restrict__ out) {
    int i = blockIdx.x * 256 + threadIdx.x;   // per 4 floats
    float4 v = ((const float4*)in)[i];
    uint2 u;
    u.x = f22u(v.x, v.y);
    u.y = f22u(v.z, v.w);
    ((uint2*)out)[i] = u;
}

// ---------------- fp16 mma.sync GEMM (K-tile 64, 3-stage, occ 2) --------------
#define SH 72                          // smem row stride (halves) for 64-half K-tile
#define HSTAGE (128 * SH)              // halves per tile = 9216
#define GEMM_SMEM (3 * 2 * HSTAGE * 2) // 110592 B -> 2 CTAs/SM

#define EPI_BIAS_H 0   // bias, half out
#define EPI_RES    1   // bias + residual(f32), f32 out
#define EPI_GELU   2   // bias + gelu, half out

__global__ __launch_bounds__(256, 2)
void gemm_tc(const __half* __restrict__ A, const __half* __restrict__ Bt,
             const float* __restrict__ bias, const float* __restrict__ resid,
             float* __restrict__ Cf, __half* __restrict__ Ch, int N, int K, int epi) {
    extern __shared__ __half smh[];
    int tid = threadIdx.x;
    int lane = tid & 31, w = tid >> 5;
    int wm = w & 3, wn = w >> 2;        // 4 m-warps x 2 n-warps
    int ar = lane >> 2, ac = lane & 3;
    int quad = lane >> 3, wi = lane & 7;
    int brow = blockIdx.y * 128, bcol = blockIdx.x * 128;

    int lrow = tid >> 1, lh = (tid & 1) * 32;   // 32-half segment
    const __half* Ap = A + (size_t)(brow + lrow) * K + lh;
    const __half* Bp = Bt + (size_t)(bcol + lrow) * K + lh;
    uint32_t sbase = smem_u32(smh);
    uint32_t dstoff = (uint32_t)(lrow * SH + lh) * 2;
    int KT = K / 64;

    uint32_t aoff = (uint32_t)((wm * 32 + wi + (quad & 1) * 8) * SH + (quad >> 1) * 8);
    uint32_t boff = (uint32_t)((wn * 64 + wi + (quad >> 1) * 8) * SH + (quad & 1) * 8);

#define GFETCH(kt_) do { \
        uint32_t ab_ = sbase + ((kt_) % 3) * (2 * HSTAGE * 2); \
        uint32_t bb_ = ab_ + HSTAGE * 2; \
        const __half* ap_ = Ap + (kt_) * 64; \
        const __half* bp_ = Bp + (kt_) * 64; \
        cp_async16(ab_ + dstoff,      ap_); \
        cp_async16(ab_ + dstoff + 16, ap_ + 8); \
        cp_async16(ab_ + dstoff + 32, ap_ + 16); \
        cp_async16(ab_ + dstoff + 48, ap_ + 24); \
        cp_async16(bb_ + dstoff,      bp_); \
        cp_async16(bb_ + dstoff + 16, bp_ + 8); \
        cp_async16(bb_ + dstoff + 32, bp_ + 16); \
        cp_async16(bb_ + dstoff + 48, bp_ + 24); \
        cp_commit(); \
    } while (0)

    GFETCH(0); GFETCH(1);

    float cf[2][8][4];
#pragma unroll
    for (int mt = 0; mt < 2; mt++)
#pragma unroll
        for (int nt = 0; nt < 8; nt++)
#pragma unroll
            for (int u = 0; u < 4; u++) cf[mt][nt][u] = 0.f;

    for (int kt = 0; kt < KT; kt++) {
        if (kt + 1 < KT) cp_wait<1>();
        else cp_wait<0>();
        __syncthreads();

        uint32_t abase = sbase + (kt % 3) * (2 * HSTAGE * 2);
        uint32_t bbase = abase + HSTAGE * 2;
#pragma unroll
        for (int ks = 0; ks < 4; ks++) {
            uint32_t af[2][4], bf[8][2];
#pragma unroll
            for (int mt = 0; mt < 2; mt++)
                ldsm4(af[mt], abase + (aoff + mt * 16 * SH + ks * 16) * 2);
#pragma unroll
            for (int i = 0; i < 4; i++) {
                uint32_t r[4];
                ldsm4(r, bbase + (boff + i * 16 * SH + ks * 16) * 2);
                bf[2 * i][0] = r[0]; bf[2 * i][1] = r[1];
                bf[2 * i + 1][0] = r[2]; bf[2 * i + 1][1] = r[3];
            }
#pragma unroll
            for (int mt = 0; mt < 2; mt++)
#pragma unroll
                for (int nt = 0; nt < 8; nt++)
                    mma16(cf[mt][nt], af[mt], bf[nt]);
        }
        if (kt + 2 < KT) GFETCH(kt + 2);
    }

    // epilogue
#pragma unroll
    for (int nt = 0; nt < 8; nt++) {
        int col = bcol + wn * 64 + nt * 8 + 2 * ac;
        float b0 = bias[col], b1 = bias[col + 1];
#pragma unroll
        for (int mt = 0; mt < 2; mt++) {
            int r0 = brow + wm * 32 + mt * 16 + ar;
            float v00 = cf[mt][nt][0] + b0, v01 = cf[mt][nt][1] + b1;
            float v10 = cf[mt][nt][2] + b0, v11 = cf[mt][nt][3] + b1;
            size_t o0 = (size_t)r0 * N + col;
            size_t o1 = (size_t)(r0 + 8) * N + col;
            if (epi == EPI_RES) {
                float2 q0 = *(const float2*)(resid + o0);
                float2 q1 = *(const float2*)(resid + o1);
                v00 += q0.x; v01 += q0.y; v10 += q1.x; v11 += q1.y;
                *(float2*)(Cf + o0) = make_float2(v00, v01);
                *(float2*)(Cf + o1) = make_float2(v10, v11);
            } else {
                if (epi == EPI_GELU) {
                    v00 = 0.5f * v00 * (1.0f + erff(v00 * 0.70710678118654752f));
                    v01 = 0.5f * v01 * (1.0f + erff(v01 * 0.70710678118654752f));
                    v10 = 0.5f * v10 * (1.0f + erff(v10 * 0.70710678118654752f));
                    v11 = 0.5f * v11 * (1.0f + erff(v11 * 0.70710678118654752f));
                }
                *(uint32_t*)(Ch + o0) = f22u(v00, v01);
                *(uint32_t*)(Ch + o1) = f22u(v10, v11);
            }
        }
    }
}

// ---------------- flash attention fp16, FA2 warp layout (R11, banked) --------
#define AH 72                                 // row stride (halves)
#define OFF_Q  0                              // 128*72
#define OFF_K  (128 * AH)                     // 2 buf x 64*72
#define OFF_V  (OFF_K + 2 * 64 * AH)          // 2 buf x 64*72
#define HTOT   (OFF_V + 2 * 64 * AH)          // 27648 halves
#define ATTN_SMEM (HTOT * 2)                  // 55296 B

__global__ __launch_bounds__(256, 2)
void attn_tc(const __half* __restrict__ QKV, __half* __restrict__ O) {
    extern __shared__ __half smh[];
    int tid = threadIdx.x;
    int lane = tid & 31, w = tid >> 5;
    int ar = lane >> 2, ac = lane & 3;
    int quad = lane >> 3, wi = lane & 7;

    int bh = blockIdx.y;
    int b = bh >> 3, h = bh & 7;
    int qbase = blockIdx.x * 128;
    const __half* Qg = QKV + (size_t)(b * NS + qbase) * QLD + h * NHD;
    const __half* Kg = QKV + (size_t)b * NS * QLD + 512 + h * NHD;
    const __half* Vg = QKV + (size_t)b * NS * QLD + 1024 + h * NHD;

    uint32_t sbase = smem_u32(smh);
    int trow = tid >> 2;            // 0..63
    int tseg = (tid & 3) * 16;      // 16-half segment

    uint32_t qoff = (uint32_t)((w * 16 + wi + (quad & 1) * 8) * AH + (quad >> 1) * 8);  // A (Q)
    uint32_t koff = (uint32_t)((wi + (quad >> 1) * 8) * AH + (quad & 1) * 8);           // B (K)
    uint32_t voff = (uint32_t)((wi + (quad & 1) * 8) * AH + (quad >> 1) * 8);           // B.trans (V)

    // Q (128 rows) + K0 + V0
    {
#pragma unroll
        for (int rr = 0; rr < 2; rr++) {
            int r = trow + rr * 64;
            const __half* qp = Qg + (size_t)r * QLD + tseg;
            uint32_t qd = sbase + (uint32_t)(OFF_Q + r * AH + tseg) * 2;
            cp_async16(qd, qp);
            cp_async16(qd + 16, qp + 8);
        }
        const __half* kp = Kg + (size_t)trow * QLD + tseg;
        const __half* vp = Vg + (size_t)trow * QLD + tseg;
        uint32_t kd = sbase + (uint32_t)(OFF_K + trow * AH + tseg) * 2;
        uint32_t vd = sbase + (uint32_t)(OFF_V + trow * AH + tseg) * 2;
        cp_async16(kd, kp); cp_async16(kd + 16, kp + 8);
        cp_async16(vd, vp); cp_async16(vd + 16, vp + 8);
    }
    cp_commit();
    cp_wait<0>();
    __syncthreads();

    // preload Q fragments (loop-invariant)
    uint32_t qf[4][4];
    uint32_t qsb = sbase + OFF_Q * 2;
#pragma unroll
    for (int ks = 0; ks < 4; ks++)
        ldsm4(qf[ks], qsb + (qoff + ks * 16) * 2);

    float of[8][4];
#pragma unroll
    for (int nt = 0; nt < 8; nt++)
#pragma unroll
        for (int u = 0; u < 4; u++) of[nt][u] = 0.f;
    float m0 = -1e30f, m1 = -1e30f, l0 = 0.f, l1 = 0.f;

    for (int ct = 0; ct < NS / 64; ct++) {
        if (ct > 0) {
            cp_wait<0>();
            __syncthreads();
        }
        if (ct + 1 < NS / 64) {
            int nb = (ct + 1) & 1;
            const __half* kn = Kg + (size_t)((ct + 1) * 64 + trow) * QLD + tseg;
            const __half* vn = Vg + (size_t)((ct + 1) * 64 + trow) * QLD + tseg;
            uint32_t kd = sbase + (uint32_t)(OFF_K + nb * 64 * AH + trow * AH + tseg) * 2;
            uint32_t vd = sbase + (uint32_t)(OFF_V + nb * 64 * AH + trow * AH + tseg) * 2;
            cp_async16(kd, kn); cp_async16(kd + 16, kn + 8);
            cp_async16(vd, vn); cp_async16(vd + 16, vn + 8);
            cp_commit();
        }

        uint32_t ksb = sbase + (OFF_K + (ct & 1) * 64 * AH) * 2;
        uint32_t vsb = sbase + (OFF_V + (ct & 1) * 64 * AH) * 2;

        // S = Q K^T  (16 rows x 64 keys per warp)
        float sf[8][4];
#pragma unroll
        for (int nt = 0; nt < 8; nt++)
#pragma unroll
            for (int u = 0; u < 4; u++) sf[nt][u] = 0.f;
#pragma unroll
        for (int ks = 0; ks < 4; ks++) {
            uint32_t bf[8][2];
#pragma unroll
            for (int i = 0; i < 4; i++) {
                uint32_t r[4];
                ldsm4(r, ksb + (koff + i * 16 * AH + ks * 16) * 2);
                bf[2 * i][0] = r[0]; bf[2 * i][1] = r[1];
                bf[2 * i + 1][0] = r[2]; bf[2 * i + 1][1] = r[3];
            }
#pragma unroll
            for (int nt = 0; nt < 8; nt++) mma16(sf[nt], qf[ks], bf[nt]);
        }

        // in-warp softmax (rows r0 = w*16+ar, r1 = r0+8)
        float mx0 = -1e30f, mx1 = -1e30f;
#pragma unroll
        for (int nt = 0; nt < 8; nt++) {
#pragma unroll
            for (int u = 0; u < 4; u++) sf[nt][u] *= 0.125f;
            mx0 = fmaxf(mx0, fmaxf(sf[nt][0], sf[nt][1]));
            mx1 = fmaxf(mx1, fmaxf(sf[nt][2], sf[nt][3]));
        }
        mx0 = fmaxf(mx0, __shfl_xor_sync(0xFFFFFFFFu, mx0, 1));
        mx0 = fmaxf(mx0, __shfl_xor_sync(0xFFFFFFFFu, mx0, 2));
        mx1 = fmaxf(mx1, __shfl_xor_sync(0xFFFFFFFFu, mx1, 1));
        mx1 = fmaxf(mx1, __shfl_xor_sync(0xFFFFFFFFu, mx1, 2));
        float mn0 = fmaxf(m0, mx0), mn1 = fmaxf(m1, mx1);
        float cr0 = __expf(m0 - mn0), cr1 = __expf(m1 - mn1);
        m0 = mn0; m1 = mn1;
#pragma unroll
        for (int nt = 0; nt < 8; nt++) {
            of[nt][0] *= cr0; of[nt][1] *= cr0;
            of[nt][2] *= cr1; of[nt][3] *= cr1;
        }

        // exp; pack P straight into A-fragments (C layout == A layout)
        uint32_t pf[4][4];
        float s0 = 0.f, s1 = 0.f;
#pragma unroll
        for (int ks = 0; ks < 4; ks++) {
            float p00 = __expf(sf[2 * ks][0] - mn0),     p01 = __expf(sf[2 * ks][1] - mn0);
            float p10 = __expf(sf[2 * ks][2] - mn1),     p11 = __expf(sf[2 * ks][3] - mn1);
            float p20 = __expf(sf[2 * ks + 1][0] - mn0), p21 = __expf(sf[2 * ks + 1][1] - mn0);
            float p30 = __expf(sf[2 * ks + 1][2] - mn1), p31 = __expf(sf[2 * ks + 1][3] - mn1);
            s0 += p00 + p01 + p20 + p21;
            s1 += p10 + p11 + p30 + p31;
            pf[ks][0] = f22u(p00, p01);
            pf[ks][1] = f22u(p10, p11);
            pf[ks][2] = f22u(p20, p21);
            pf[ks][3] = f22u(p30, p31);
        }
        s0 += __shfl_xor_sync(0xFFFFFFFFu, s0, 1);
        s0 += __shfl_xor_sync(0xFFFFFFFFu, s0, 2);
        s1 += __shfl_xor_sync(0xFFFFFFFFu, s1, 1);
        s1 += __shfl_xor_sync(0xFFFFFFFFu, s1, 2);
        l0 = l0 * cr0 + s0;
        l1 = l1 * cr1 + s1;

        // O += P V   (V via ldmatrix.trans: k = keys, n = feats)
#pragma unroll
        for (int ks = 0; ks < 4; ks++) {
            uint32_t bf[8][2];
#pragma unroll
            for (int i = 0; i < 4; i++) {
                uint32_t r[4];
                ldsm4t(r, vsb + (voff + ks * 16 * AH + i * 16) * 2);
                bf[2 * i][0] = r[0]; bf[2 * i][1] = r[1];
                bf[2 * i + 1][0] = r[2]; bf[2 * i + 1][1] = r[3];
            }
#pragma unroll
            for (int nt = 0; nt < 8; nt++) mma16(of[nt], pf[ks], bf[nt]);
        }
    }

    float i0 = 1.0f / l0, i1 = 1.0f / l1;
    int r0 = w * 16 + ar;
#pragma unroll
    for (int nt = 0; nt < 8; nt++) {
        int col = h * NHD + nt * 8 + 2 * ac;
        size_t o0 = (size_t)(b * NS + qbase + r0) * ND + col;
        size_t o1 = (size_t)(b * NS + qbase + r0 + 8) * ND + col;
        *(uint32_t*)(O + o0) = f22u(of[nt][0] * i0, of[nt][1] * i0);
        *(uint32_t*)(O + o1) = f22u(of[nt][2] * i1, of[nt][3] * i1);
    }
}

// ---------------- layernorm --------------------------------------------------
__global__ __launch_bounds__(128)
void layernorm_kernel(const float* __restrict__ X, const float* __restrict__ g,
                      const float* __restrict__ beta, float* __restrict__ Y,
                      __half* __restrict__ Yh) {
    __shared__ float ssum[4], ssq[4];
    int row = blockIdx.x;
    int t = threadIdx.x;
    float4 v = ((const float4*)(X + (size_t)row * ND))[t];
    float s = v.x + v.y + v.z + v.w;
    float q = v.x * v.x + v.y * v.y + v.z * v.z + v.w * v.w;
#pragma unroll
    for (int off = 16; off > 0; off >>= 1) {
        s += __shfl_xor_sync(0xFFFFFFFFu, s, off);
        q += __shfl_xor_sync(0xFFFFFFFFu, q, off);
    }
    int w = t >> 5;
    if ((t & 31) == 0) { ssum[w] = s; ssq[w] = q; }
    __syncthreads();
    s = ssum[0] + ssum[1] + ssum[2] + ssum[3];
    q = ssq[0] + ssq[1] + ssq[2] + ssq[3];
    float mu = s * (1.0f / 512.0f);
    float var = q * (1.0f / 512.0f) - mu * mu;
    float rstd = rsqrtf(var + 1e-12f);
    float4 gv = ((const float4*)g)[t];
    float4 bv = ((const float4*)beta)[t];
    float4 y;
    y.x = (v.x - mu) * rstd * gv.x + bv.x;
    y.y = (v.y - mu) * rstd * gv.y + bv.y;
    y.z = (v.z - mu) * rstd * gv.z + bv.z;
    y.w = (v.w - mu) * rstd * gv.w + bv.w;
    ((float4*)(Y + (size_t)row * ND))[t] = y;
    if (Yh) {
        uint2 u;
        u.x = f22u(y.x, y.y);
        u.y = f22u(y.z, y.w);
        ((uint2*)(Yh + (size_t)row * ND))[t] = u;
    }
}

// ---------------- launch -----------------------------------------------------
extern "C" void kernel_launch(void* const* d_in, const int* in_sizes, int n_in,
                              void* d_out, int out_size) {
    const float* x    = (const float*)d_in[0];
    const float* Wq   = (const float*)d_in[1];
    const float* bq   = (const float*)d_in[2];
    const float* Wk   = (const float*)d_in[3];
    const float* bk   = (const float*)d_in[4];
    const float* Wv   = (const float*)d_in[5];
    const float* bv   = (const float*)d_in[6];
    const float* Wo   = (const float*)d_in[7];
    const float* bo   = (const float*)d_in[8];
    const float* W1   = (const float*)d_in[9];
    const float* b1   = (const float*)d_in[10];
    const float* W2   = (const float*)d_in[11];
    const float* b2   = (const float*)d_in[12];
    const float* ln1g = (const float*)d_in[13];
    const float* ln1b = (const float*)d_in[14];
    const float* ln2g = (const float*)d_in[15];
    const float* ln2b = (const float*)d_in[16];

    __half *wqkvth, *woth, *w1th, *w2th, *xh, *qkvh, *attnh, *x1h, *hh;
    float *bqkv, *res1, *x1, *res2;
    cudaGetSymbolAddress((void**)&wqkvth, g_wqkvth);
    cudaGetSymbolAddress((void**)&bqkv,   g_bqkv);
    cudaGetSymbolAddress((void**)&woth,   g_woth);
    cudaGetSymbolAddress((void**)&w1th,   g_w1th);
    cudaGetSymbolAddress((void**)&w2th,   g_w2th);
    cudaGetSymbolAddress((void**)&xh,     g_xh);
    cudaGetSymbolAddress((void**)&qkvh,   g_qkvh);
    cudaGetSymbolAddress((void**)&attnh,  g_attnh);
    cudaGetSymbolAddress((void**)&res1,   g_res1);
    cudaGetSymbolAddress((void**)&x1,     g_x1);
    cudaGetSymbolAddress((void**)&x1h,    g_x1h);
    cudaGetSymbolAddress((void**)&hh,     g_hh);
    cudaGetSymbolAddress((void**)&res2,   g_res2);

    cudaFuncSetAttribute(gemm_tc, cudaFuncAttributeMaxDynamicSharedMemorySize, GEMM_SMEM);
    cudaFuncSetAttribute(attn_tc, cudaFuncAttributeMaxDynamicSharedMemorySize, ATTN_SMEM);

    // prep (fused weight transposes + bias pack + x convert)
    prep_w_t<<<3072, 256>>>(Wq, Wk, Wv, Wo, W1, W2, wqkvth, woth, w1th, w2th);
    pack_qkvb_kernel<<<6, 256>>>(bq, bk, bv, bqkv);
    cvt_half_kernel<<<(NROW * ND / 4) / 256, 256>>>(x, xh);

    // QKV fused projection (half out)
    gemm_tc<<<dim3(12, 64), 256, GEMM_SMEM>>>(xh, wqkvth, bqkv, nullptr, nullptr, qkvh, 1536, 512, EPI_BIAS_H);

    // flash attention (FA2 layout)
    attn_tc<<<dim3(NS / 128, NB * NH), 256, ATTN_SMEM>>>(qkvh, attnh);

    // Wo + residual(x) -> f32; LN1 -> x1 (f32) + x1h (half)
    gemm_tc<<<dim3(4, 64), 256, GEMM_SMEM>>>(attnh, woth, bo, x, res1, nullptr, 512, 512, EPI_RES);
    layernorm_kernel<<<NROW, 128>>>(res1, ln1g, ln1b, x1, x1h);

    // FFN
    gemm_tc<<<dim3(16, 64), 256, GEMM_SMEM>>>(x1h, w1th, b1, nullptr, nullptr, hh, 2048, 512, EPI_GELU);
    gemm_tc<<<dim3(4, 64), 256, GEMM_SMEM>>>(hh, w2th, b2, x1, res2, nullptr, 512, 2048, EPI_RES);

    // LN2 -> out
    layernorm_kernel<<<NROW, 128>>>(res2, ln2g, ln2b, (float*)d_out, nullptr);
}

// round 16
// speedup vs baseline: 1.0853x; 1.0853x over previous
#include <cuda_runtime.h>
#include <cuda_fp16.h>
#include <math.h>
#include <cstdint>

// Problem dims
#define NB 4
#define NS 2048
#define ND 512
#define NH 8
#define NHD 64
#define NF 2048
#define NROW (NB * NS)   // 8192
#define QLD 1536         // fused qkv row stride (halves)

// ---------------- scratch ----------------------------------------------------
__device__ __half g_wqkvth[1536 * 512];
__device__ float  g_bqkv[1536];
__device__ __half g_woth[512 * 512];
__device__ __half g_w1th[2048 * 512];
__device__ __half g_w2th[512 * 2048];
__device__ __half g_xh[NROW * ND];
__device__ __half g_qkvh[NROW * 1536];
__device__ __half g_attnh[NROW * ND];
__device__ float  g_res1[NROW * ND];
__device__ float  g_x1[NROW * ND];
__device__ __half g_x1h[NROW * ND];
__device__ __half g_hh[NROW * NF];
__device__ float  g_res2[NROW * ND];

// ---------------- helpers ----------------------------------------------------
__device__ __forceinline__ uint32_t smem_u32(const void* p) {
    uint32_t a;
    asm("{ .reg .u64 t; cvta.to.shared.u64 t, %1; cvt.u32.u64 %0, t; }" : "=r"(a) : "l"(p));
    return a;
}
__device__ __forceinline__ void cp_async16(uint32_t sa, const void* ga) {
    asm volatile("cp.async.cg.shared.global [%0], [%1], 16;" :: "r"(sa), "l"(ga) : "memory");
}
__device__ __forceinline__ void cp_commit() { asm volatile("cp.async.commit_group;" ::: "memory"); }
template <int N> __device__ __forceinline__ void cp_wait() {
    asm volatile("cp.async.wait_group %0;" :: "n"(N) : "memory");
}
// D += A*B  (m16n8k16 fp16 in, fp32 accum)
__device__ __forceinline__ void mma16(float* c, const uint32_t* a, const uint32_t* b) {
    asm volatile("mma.sync.aligned.m16n8k16.row.col.f32.f16.f16.f32 "
                 "{%0,%1,%2,%3}, {%4,%5,%6,%7}, {%8,%9}, {%0,%1,%2,%3};"
                 : "+f"(c[0]), "+f"(c[1]), "+f"(c[2]), "+f"(c[3])
                 : "r"(a[0]), "r"(a[1]), "r"(a[2]), "r"(a[3]), "r"(b[0]), "r"(b[1]));
}
__device__ __forceinline__ void ldsm4(uint32_t* r, uint32_t addr) {
    asm volatile("ldmatrix.sync.aligned.m8n8.x4.shared.b16 {%0,%1,%2,%3}, [%4];"
                 : "=r"(r[0]), "=r"(r[1]), "=r"(r[2]), "=r"(r[3]) : "r"(addr));
}
__device__ __forceinline__ void ldsm4t(uint32_t* r, uint32_t addr) {
    asm volatile("ldmatrix.sync.aligned.m8n8.x4.trans.shared.b16 {%0,%1,%2,%3}, [%4];"
                 : "=r"(r[0]), "=r"(r[1]), "=r"(r[2]), "=r"(r[3]) : "r"(addr));
}
__device__ __forceinline__ uint32_t f22u(float a, float b) {
    __half2 t = __floats2half2_rn(a, b);
    return *(uint32_t*)&t;
}

// ---------------- fused weight-transpose prep (single launch) ----------------
// 1D grid of 3072 32x32 tiles:
//   [0,768)    : QKV pack  (24 slices x (16 k-tiles x 2 e-tiles))
//   [768,1024) : Wo   (K=512,  N=512)
//   [1024,2048): W1   (K=512,  N=2048)
//   [2048,3072): W2   (K=2048, N=512)
__global__ void prep_w_t(const float* __restrict__ Wq, const float* __restrict__ Wk,
                         const float* __restrict__ Wv, const float* __restrict__ Wo,
                         const float* __restrict__ W1, const float* __restrict__ W2,
                         __half* __restrict__ oqkv, __half* __restrict__ owo,
                         __half* __restrict__ ow1, __half* __restrict__ ow2) {
    __shared__ float tile[32][33];
    int id = blockIdx.x;
    const float* in;
    __half* out;
    int K, N, k0, n0;
    size_t outbase;
    if (id < 768) {
        int slice = id >> 5, rem = id & 31;
        int sel = slice >> 3, h = slice & 7;
        in = (sel == 0 ? Wq : (sel == 1 ? Wk : Wv)) + (size_t)h * 512 * 64;
        out = oqkv; K = 512; N = 64;
        k0 = (rem & 15) * 32; n0 = (rem >> 4) * 32;
        outbase = (size_t)(sel * 512 + h * 64);
    } else if (id < 1024) {
        int r = id - 768;
        in = Wo; out = owo; K = 512; N = 512;
        n0 = (r & 15) * 32; k0 = (r >> 4) * 32; outbase = 0;
    } else if (id < 2048) {
        int r = id - 1024;
        in = W1; out = ow1; K = 512; N = 2048;
        n0 = (r & 63) * 32; k0 = (r >> 6) * 32; outbase = 0;
    } else {
        int r = id - 2048;
        in = W2; out = ow2; K = 2048; N = 512;
        n0 = (r & 15) * 32; k0 = (r >> 4) * 32; outbase = 0;
    }
    int tx = threadIdx.x & 31, ty = threadIdx.x >> 5;
#pragma unroll
    for (int i = 0; i < 4; i++)
        tile[ty + i * 8][tx] = in[(size_t)(k0 + ty + i * 8) * N + n0 + tx];
    __syncthreads();
#pragma unroll
    for (int i = 0; i < 4; i++)
        out[(outbase + n0 + ty + i * 8) * (size_t)K + k0 + tx] =
            __float2half_rn(tile[tx][ty + i * 8]);
}
__global__ void pack_qkvb_kernel(const float* __restrict__ bq, const float* __restrict__ bk,
                                 const float* __restrict__ bv, float* __restrict__ out) {
    int n = blockIdx.x * 256 + threadIdx.x;
    if (n >= 1536) return;
    int sel = n >> 9, r = n & 511;
    const float* b = sel == 0 ? bq : (sel == 1 ? bk : bv);
    out[n] = b[r];
}
__global__ void cvt_half_kernel(const float* __restrict__ in, __half* __restrict__ out) {
    int i = blockIdx.x * 256 + threadIdx.x;   // per 4 floats
    float4 v = ((const float4*)in)[i];
    uint2 u;
    u.x = f22u(v.x, v.y);
    u.y = f22u(v.z, v.w);
    ((uint2*)out)[i] = u;
}

// ---------------- fp16 mma.sync GEMM (R11: K-tile 32, 4-stage, occ 2) ---------
#define SH 40                          // smem row stride (halves)
#define HSTAGE (128 * SH)              // halves per tile = 5120
#define GEMM_SMEM (4 * 2 * HSTAGE * 2) // 81920 B -> 2 CTAs/SM

#define EPI_BIAS_H 0   // bias, half out
#define EPI_RES    1   // bias + residual(f32), f32 out
#define EPI_GELU   2   // bias + gelu, half out

__global__ __launch_bounds__(256, 2)
void gemm_tc(const __half* __restrict__ A, const __half* __restrict__ Bt,
             const float* __restrict__ bias, const float* __restrict__ resid,
             float* __restrict__ Cf, __half* __restrict__ Ch, int N, int K, int epi) {
    extern __shared__ __half smh[];
    int tid = threadIdx.x;
    int lane = tid & 31, w = tid >> 5;
    int wm = w & 3, wn = w >> 2;        // 4 m-warps x 2 n-warps
    int ar = lane >> 2, ac = lane & 3;
    int quad = lane >> 3, wi = lane & 7;
    int brow = blockIdx.y * 128, bcol = blockIdx.x * 128;

    int lrow = tid >> 1, lh = (tid & 1) * 16;   // 16-half segment
    const __half* Ap = A + (size_t)(brow + lrow) * K + lh;
    const __half* Bp = Bt + (size_t)(bcol + lrow) * K + lh;
    uint32_t sbase = smem_u32(smh);
    uint32_t dstoff = (uint32_t)(lrow * SH + lh) * 2;
    int KT = K / 32;

    uint32_t aoff = (uint32_t)((wm * 32 + wi + (quad & 1) * 8) * SH + (quad >> 1) * 8);
    uint32_t boff = (uint32_t)((wn * 64 + wi + (quad >> 1) * 8) * SH + (quad & 1) * 8);

#define GFETCH(kt_) do { \
        uint32_t ab_ = sbase + ((kt_) & 3) * (2 * HSTAGE * 2); \
        uint32_t bb_ = ab_ + HSTAGE * 2; \
        const __half* ap_ = Ap + (kt_) * 32; \
        const __half* bp_ = Bp + (kt_) * 32; \
        cp_async16(ab_ + dstoff,      ap_); \
        cp_async16(ab_ + dstoff + 16, ap_ + 8); \
        cp_async16(bb_ + dstoff,      bp_); \
        cp_async16(bb_ + dstoff + 16, bp_ + 8); \
        cp_commit(); \
    } while (0)

    GFETCH(0); GFETCH(1); GFETCH(2);

    float cf[2][8][4];
#pragma unroll
    for (int mt = 0; mt < 2; mt++)
#pragma unroll
        for (int nt = 0; nt < 8; nt++)
#pragma unroll
            for (int u = 0; u < 4; u++) cf[mt][nt][u] = 0.f;

    for (int kt = 0; kt < KT; kt++) {
        int pend = KT - kt;
        if (pend >= 3) cp_wait<2>();
        else if (pend == 2) cp_wait<1>();
        else cp_wait<0>();
        __syncthreads();

        uint32_t abase = sbase + (kt & 3) * (2 * HSTAGE * 2);
        uint32_t bbase = abase + HSTAGE * 2;
#pragma unroll
        for (int ks = 0; ks < 2; ks++) {
            uint32_t af[2][4], bf[8][2];
#pragma unroll
            for (int mt = 0; mt < 2; mt++)
                ldsm4(af[mt], abase + (aoff + mt * 16 * SH + ks * 16) * 2);
#pragma unroll
            for (int i = 0; i < 4; i++) {
                uint32_t r[4];
                ldsm4(r, bbase + (boff + i * 16 * SH + ks * 16) * 2);
                bf[2 * i][0] = r[0]; bf[2 * i][1] = r[1];
                bf[2 * i + 1][0] = r[2]; bf[2 * i + 1][1] = r[3];
            }
#pragma unroll
            for (int mt = 0; mt < 2; mt++)
#pragma unroll
                for (int nt = 0; nt < 8; nt++)
                    mma16(cf[mt][nt], af[mt], bf[nt]);
        }
        if (kt + 3 < KT) GFETCH(kt + 3);
    }

    // epilogue
#pragma unroll
    for (int nt = 0; nt < 8; nt++) {
        int col = bcol + wn * 64 + nt * 8 + 2 * ac;
        float b0 = bias[col], b1 = bias[col + 1];
#pragma unroll
        for (int mt = 0; mt < 2; mt++) {
            int r0 = brow + wm * 32 + mt * 16 + ar;
            float v00 = cf[mt][nt][0] + b0, v01 = cf[mt][nt][1] + b1;
            float v10 = cf[mt][nt][2] + b0, v11 = cf[mt][nt][3] + b1;
            size_t o0 = (size_t)r0 * N + col;
            size_t o1 = (size_t)(r0 + 8) * N + col;
            if (epi == EPI_RES) {
                float2 q0 = *(const float2*)(resid + o0);
                float2 q1 = *(const float2*)(resid + o1);
                v00 += q0.x; v01 += q0.y; v10 += q1.x; v11 += q1.y;
                *(float2*)(Cf + o0) = make_float2(v00, v01);
                *(float2*)(Cf + o1) = make_float2(v10, v11);
            } else {
                if (epi == EPI_GELU) {
                    v00 = 0.5f * v00 * (1.0f + erff(v00 * 0.70710678118654752f));
                    v01 = 0.5f * v01 * (1.0f + erff(v01 * 0.70710678118654752f));
                    v10 = 0.5f * v10 * (1.0f + erff(v10 * 0.70710678118654752f));
                    v11 = 0.5f * v11 * (1.0f + erff(v11 * 0.70710678118654752f));
                }
                *(uint32_t*)(Ch + o0) = f22u(v00, v01);
                *(uint32_t*)(Ch + o1) = f22u(v10, v11);
            }
        }
    }
}

// ---------------- flash attention fp16, FA2 warp layout (R11, banked) --------
#define AH 72                                 // row stride (halves)
#define OFF_Q  0                              // 128*72
#define OFF_K  (128 * AH)                     // 2 buf x 64*72
#define OFF_V  (OFF_K + 2 * 64 * AH)          // 2 buf x 64*72
#define HTOT   (OFF_V + 2 * 64 * AH)          // 27648 halves
#define ATTN_SMEM (HTOT * 2)                  // 55296 B

__global__ __launch_bounds__(256, 2)
void attn_tc(const __half* __restrict__ QKV, __half* __restrict__ O) {
    extern __shared__ __half smh[];
    int tid = threadIdx.x;
    int lane = tid & 31, w = tid >> 5;
    int ar = lane >> 2, ac = lane & 3;
    int quad = lane >> 3, wi = lane & 7;

    int bh = blockIdx.y;
    int b = bh >> 3, h = bh & 7;
    int qbase = blockIdx.x * 128;
    const __half* Qg = QKV + (size_t)(b * NS + qbase) * QLD + h * NHD;
    const __half* Kg = QKV + (size_t)b * NS * QLD + 512 + h * NHD;
    const __half* Vg = QKV + (size_t)b * NS * QLD + 1024 + h * NHD;

    uint32_t sbase = smem_u32(smh);
    int trow = tid >> 2;            // 0..63
    int tseg = (tid & 3) * 16;      // 16-half segment

    uint32_t qoff = (uint32_t)((w * 16 + wi + (quad & 1) * 8) * AH + (quad >> 1) * 8);  // A (Q)
    uint32_t koff = (uint32_t)((wi + (quad >> 1) * 8) * AH + (quad & 1) * 8);           // B (K)
    uint32_t voff = (uint32_t)((wi + (quad & 1) * 8) * AH + (quad >> 1) * 8);           // B.trans (V)

    // Q (128 rows) + K0 + V0
    {
#pragma unroll
        for (int rr = 0; rr < 2; rr++) {
            int r = trow + rr * 64;
            const __half* qp = Qg + (size_t)r * QLD + tseg;
            uint32_t qd = sbase + (uint32_t)(OFF_Q + r * AH + tseg) * 2;
            cp_async16(qd, qp);
            cp_async16(qd + 16, qp + 8);
        }
        const __half* kp = Kg + (size_t)trow * QLD + tseg;
        const __half* vp = Vg + (size_t)trow * QLD + tseg;
        uint32_t kd = sbase + (uint32_t)(OFF_K + trow * AH + tseg) * 2;
        uint32_t vd = sbase + (uint32_t)(OFF_V + trow * AH + tseg) * 2;
        cp_async16(kd, kp); cp_async16(kd + 16, kp + 8);
        cp_async16(vd, vp); cp_async16(vd + 16, vp + 8);
    }
    cp_commit();
    cp_wait<0>();
    __syncthreads();

    // preload Q fragments (loop-invariant)
    uint32_t qf[4][4];
    uint32_t qsb = sbase + OFF_Q * 2;
#pragma unroll
    for (int ks = 0; ks < 4; ks++)
        ldsm4(qf[ks], qsb + (qoff + ks * 16) * 2);

    float of[8][4];
#pragma unroll
    for (int nt = 0; nt < 8; nt++)
#pragma unroll
        for (int u = 0; u < 4; u++) of[nt][u] = 0.f;
    float m0 = -1e30f, m1 = -1e30f, l0 = 0.f, l1 = 0.f;

    for (int ct = 0; ct < NS / 64; ct++) {
        if (ct > 0) {
            cp_wait<0>();
            __syncthreads();
        }
        if (ct + 1 < NS / 64) {
            int nb = (ct + 1) & 1;
            const __half* kn = Kg + (size_t)((ct + 1) * 64 + trow) * QLD + tseg;
            const __half* vn = Vg + (size_t)((ct + 1) * 64 + trow) * QLD + tseg;
            uint32_t kd = sbase + (uint32_t)(OFF_K + nb * 64 * AH + trow * AH + tseg) * 2;
            uint32_t vd = sbase + (uint32_t)(OFF_V + nb * 64 * AH + trow * AH + tseg) * 2;
            cp_async16(kd, kn); cp_async16(kd + 16, kn + 8);
            cp_async16(vd, vn); cp_async16(vd + 16, vn + 8);
            cp_commit();
        }

        uint32_t ksb = sbase + (OFF_K + (ct & 1) * 64 * AH) * 2;
        uint32_t vsb = sbase + (OFF_V + (ct & 1) * 64 * AH) * 2;

        // S = Q K^T  (16 rows x 64 keys per warp)
        float sf[8][4];
#pragma unroll
        for (int nt = 0; nt < 8; nt++)
#pragma unroll
            for (int u = 0; u < 4; u++) sf[nt][u] = 0.f;
#pragma unroll
        for (int ks = 0; ks < 4; ks++) {
            uint32_t bf[8][2];
#pragma unroll
            for (int i = 0; i < 4; i++) {
                uint32_t r[4];
                ldsm4(r, ksb + (koff + i * 16 * AH + ks * 16) * 2);
                bf[2 * i][0] = r[0]; bf[2 * i][1] = r[1];
                bf[2 * i + 1][0] = r[2]; bf[2 * i + 1][1] = r[3];
            }
#pragma unroll
            for (int nt = 0; nt < 8; nt++) mma16(sf[nt], qf[ks], bf[nt]);
        }

        // in-warp softmax (rows r0 = w*16+ar, r1 = r0+8)
        float mx0 = -1e30f, mx1 = -1e30f;
#pragma unroll
        for (int nt = 0; nt < 8; nt++) {
#pragma unroll
            for (int u = 0; u < 4; u++) sf[nt][u] *= 0.125f;
            mx0 = fmaxf(mx0, fmaxf(sf[nt][0], sf[nt][1]));
            mx1 = fmaxf(mx1, fmaxf(sf[nt][2], sf[nt][3]));
        }
        mx0 = fmaxf(mx0, __shfl_xor_sync(0xFFFFFFFFu, mx0, 1));
        mx0 = fmaxf(mx0, __shfl_xor_sync(0xFFFFFFFFu, mx0, 2));
        mx1 = fmaxf(mx1, __shfl_xor_sync(0xFFFFFFFFu, mx1, 1));
        mx1 = fmaxf(mx1, __shfl_xor_sync(0xFFFFFFFFu, mx1, 2));
        float mn0 = fmaxf(m0, mx0), mn1 = fmaxf(m1, mx1);
        float cr0 = __expf(m0 - mn0), cr1 = __expf(m1 - mn1);
        m0 = mn0; m1 = mn1;
#pragma unroll
        for (int nt = 0; nt < 8; nt++) {
            of[nt][0] *= cr0; of[nt][1] *= cr0;
            of[nt][2] *= cr1; of[nt][3] *= cr1;
        }

        // exp; pack P straight into A-fragments (C layout == A layout)
        uint32_t pf[4][4];
        float s0 = 0.f, s1 = 0.f;
#pragma unroll
        for (int ks = 0; ks < 4; ks++) {
            float p00 = __expf(sf[2 * ks][0] - mn0),     p01 = __expf(sf[2 * ks][1] - mn0);
            float p10 = __expf(sf[2 * ks][2] - mn1),     p11 = __expf(sf[2 * ks][3] - mn1);
            float p20 = __expf(sf[2 * ks + 1][0] - mn0), p21 = __expf(sf[2 * ks + 1][1] - mn0);
            float p30 = __expf(sf[2 * ks + 1][2] - mn1), p31 = __expf(sf[2 * ks + 1][3] - mn1);
            s0 += p00 + p01 + p20 + p21;
            s1 += p10 + p11 + p30 + p31;
            pf[ks][0] = f22u(p00, p01);
            pf[ks][1] = f22u(p10, p11);
            pf[ks][2] = f22u(p20, p21);
            pf[ks][3] = f22u(p30, p31);
        }
        s0 += __shfl_xor_sync(0xFFFFFFFFu, s0, 1);
        s0 += __shfl_xor_sync(0xFFFFFFFFu, s0, 2);
        s1 += __shfl_xor_sync(0xFFFFFFFFu, s1, 1);
        s1 += __shfl_xor_sync(0xFFFFFFFFu, s1, 2);
        l0 = l0 * cr0 + s0;
        l1 = l1 * cr1 + s1;

        // O += P V   (V via ldmatrix.trans: k = keys, n = feats)
#pragma unroll
        for (int ks = 0; ks < 4; ks++) {
            uint32_t bf[8][2];
#pragma unroll
            for (int i = 0; i < 4; i++) {
                uint32_t r[4];
                ldsm4t(r, vsb + (voff + ks * 16 * AH + i * 16) * 2);
                bf[2 * i][0] = r[0]; bf[2 * i][1] = r[1];
                bf[2 * i + 1][0] = r[2]; bf[2 * i + 1][1] = r[3];
            }
#pragma unroll
            for (int nt = 0; nt < 8; nt++) mma16(of[nt], pf[ks], bf[nt]);
        }
    }

    float i0 = 1.0f / l0, i1 = 1.0f / l1;
    int r0 = w * 16 + ar;
#pragma unroll
    for (int nt = 0; nt < 8; nt++) {
        int col = h * NHD + nt * 8 + 2 * ac;
        size_t o0 = (size_t)(b * NS + qbase + r0) * ND + col;
        size_t o1 = (size_t)(b * NS + qbase + r0 + 8) * ND + col;
        *(uint32_t*)(O + o0) = f22u(of[nt][0] * i0, of[nt][1] * i0);
        *(uint32_t*)(O + o1) = f22u(of[nt][2] * i1, of[nt][3] * i1);
    }
}

// ---------------- layernorm --------------------------------------------------
__global__ __launch_bounds__(128)
void layernorm_kernel(const float* __restrict__ X, const float* __restrict__ g,
                      const float* __restrict__ beta, float* __restrict__ Y,
                      __half* __restrict__ Yh) {
    __shared__ float ssum[4], ssq[4];
    int row = blockIdx.x;
    int t = threadIdx.x;
    float4 v = ((const float4*)(X + (size_t)row * ND))[t];
    float s = v.x + v.y + v.z + v.w;
    float q = v.x * v.x + v.y * v.y + v.z * v.z + v.w * v.w;
#pragma unroll
    for (int off = 16; off > 0; off >>= 1) {
        s += __shfl_xor_sync(0xFFFFFFFFu, s, off);
        q += __shfl_xor_sync(0xFFFFFFFFu, q, off);
    }
    int w = t >> 5;
    if ((t & 31) == 0) { ssum[w] = s; ssq[w] = q; }
    __syncthreads();
    s = ssum[0] + ssum[1] + ssum[2] + ssum[3];
    q = ssq[0] + ssq[1] + ssq[2] + ssq[3];
    float mu = s * (1.0f / 512.0f);
    float var = q * (1.0f / 512.0f) - mu * mu;
    float rstd = rsqrtf(var + 1e-12f);
    float4 gv = ((const float4*)g)[t];
    float4 bv = ((const float4*)beta)[t];
    float4 y;
    y.x = (v.x - mu) * rstd * gv.x + bv.x;
    y.y = (v.y - mu) * rstd * gv.y + bv.y;
    y.z = (v.z - mu) * rstd * gv.z + bv.z;
    y.w = (v.w - mu) * rstd * gv.w + bv.w;
    ((float4*)(Y + (size_t)row * ND))[t] = y;
    if (Yh) {
        uint2 u;
        u.x = f22u(y.x, y.y);
        u.y = f22u(y.z, y.w);
        ((uint2*)(Yh + (size_t)row * ND))[t] = u;
    }
}

// ---------------- launch -----------------------------------------------------
extern "C" void kernel_launch(void* const* d_in, const int* in_sizes, int n_in,
                              void* d_out, int out_size) {
    const float* x    = (const float*)d_in[0];
    const float* Wq   = (const float*)d_in[1];
    const float* bq   = (const float*)d_in[2];
    const float* Wk   = (const float*)d_in[3];
    const float* bk   = (const float*)d_in[4];
    const float* Wv   = (const float*)d_in[5];
    const float* bv   = (const float*)d_in[6];
    const float* Wo   = (const float*)d_in[7];
    const float* bo   = (const float*)d_in[8];
    const float* W1   = (const float*)d_in[9];
    const float* b1   = (const float*)d_in[10];
    const float* W2   = (const float*)d_in[11];
    const float* b2   = (const float*)d_in[12];
    const float* ln1g = (const float*)d_in[13];
    const float* ln1b = (const float*)d_in[14];
    const float* ln2g = (const float*)d_in[15];
    const float* ln2b = (const float*)d_in[16];

    __half *wqkvth, *woth, *w1th, *w2th, *xh, *qkvh, *attnh, *x1h, *hh;
    float *bqkv, *res1, *x1, *res2;
    cudaGetSymbolAddress((void**)&wqkvth, g_wqkvth);
    cudaGetSymbolAddress((void**)&bqkv,   g_bqkv);
    cudaGetSymbolAddress((void**)&woth,   g_woth);
    cudaGetSymbolAddress((void**)&w1th,   g_w1th);
    cudaGetSymbolAddress((void**)&w2th,   g_w2th);
    cudaGetSymbolAddress((void**)&xh,     g_xh);
    cudaGetSymbolAddress((void**)&qkvh,   g_qkvh);
    cudaGetSymbolAddress((void**)&attnh,  g_attnh);
    cudaGetSymbolAddress((void**)&res1,   g_res1);
    cudaGetSymbolAddress((void**)&x1,     g_x1);
    cudaGetSymbolAddress((void**)&x1h,    g_x1h);
    cudaGetSymbolAddress((void**)&hh,     g_hh);
    cudaGetSymbolAddress((void**)&res2,   g_res2);

    cudaFuncSetAttribute(gemm_tc, cudaFuncAttributeMaxDynamicSharedMemorySize, GEMM_SMEM);
    cudaFuncSetAttribute(attn_tc, cudaFuncAttributeMaxDynamicSharedMemorySize, ATTN_SMEM);

    // prep (fused weight transposes + bias pack + x convert)
    prep_w_t<<<3072, 256>>>(Wq, Wk, Wv, Wo, W1, W2, wqkvth, woth, w1th, w2th);
    pack_qkvb_kernel<<<6, 256>>>(bq, bk, bv, bqkv);
    cvt_half_kernel<<<(NROW * ND / 4) / 256, 256>>>(x, xh);

    // QKV fused projection (half out)
    gemm_tc<<<dim3(12, 64), 256, GEMM_SMEM>>>(xh, wqkvth, bqkv, nullptr, nullptr, qkvh, 1536, 512, EPI_BIAS_H);

    // flash attention (FA2 layout)
    attn_tc<<<dim3(NS / 128, NB * NH), 256, ATTN_SMEM>>>(qkvh, attnh);

    // Wo + residual(x) -> f32; LN1 -> x1 (f32) + x1h (half)
    gemm_tc<<<dim3(4, 64), 256, GEMM_SMEM>>>(attnh, woth, bo, x, res1, nullptr, 512, 512, EPI_RES);
    layernorm_kernel<<<NROW, 128>>>(res1, ln1g, ln1b, x1, x1h);

    // FFN
    gemm_tc<<<dim3(16, 64), 256, GEMM_SMEM>>>(x1h, w1th, b1, nullptr, nullptr, hh, 2048, 512, EPI_GELU);
    gemm_tc<<<dim3(4, 64), 256, GEMM_SMEM>>>(hh, w2th, b2, x1, res2, nullptr, 512, 2048, EPI_RES);

    // LN2 -> out
    layernorm_kernel<<<NROW, 128>>>(res2, ln2g, ln2b, (float*)d_out, nullptr);
}